// round 6
// baseline (speedup 1.0000x reference)
#include <cuda_runtime.h>
#include <cuda_bf16.h>
#include <cuda_fp16.h>
#include <cstdint>

#define HF 128
#define NNODES 100000
#define NODES_PAD 100096
#define MTILES 782   // ceil(100000/128)
#define AST 136      // padded row stride in halves (272B)

// ---------------- device scratch ----------------
__device__ __half g_P[(size_t)3 * NODES_PAD * HF];   // 76.9 MB fp16 P tables
__device__ __half g_Bf[3][128 * AST];                // fp16 padded B images
__device__ int g_is64;

// ---------------- helpers ----------------
static __device__ __forceinline__ void ldsm4(uint32_t* r, const void* p) {
    uint32_t a = (uint32_t)__cvta_generic_to_shared(p);
    asm volatile("ldmatrix.sync.aligned.m8n8.x4.shared.b16 {%0,%1,%2,%3}, [%4];"
                 : "=r"(r[0]), "=r"(r[1]), "=r"(r[2]), "=r"(r[3]) : "r"(a));
}
static __device__ __forceinline__ void mma_f16(float* c, const uint32_t* a,
                                               uint32_t b0, uint32_t b1) {
    asm volatile(
        "mma.sync.aligned.m16n8k16.row.col.f32.f16.f16.f32 "
        "{%0,%1,%2,%3}, {%4,%5,%6,%7}, {%8,%9}, {%0,%1,%2,%3};"
        : "+f"(c[0]), "+f"(c[1]), "+f"(c[2]), "+f"(c[3])
        : "r"(a[0]), "r"(a[1]), "r"(a[2]), "r"(a[3]), "r"(b0), "r"(b1));
}
static __device__ __forceinline__ void cpa16(void* s, const void* g) {
    uint32_t sa = (uint32_t)__cvta_generic_to_shared(s);
    asm volatile("cp.async.ca.shared.global [%0], [%1], 16;" :: "r"(sa), "l"(g));
}
#define CP_COMMIT() asm volatile("cp.async.commit_group;" ::: "memory")
#define CP_WAIT0()  asm volatile("cp.async.wait_group 0;" ::: "memory")

// ---------------- kernel 0: detect triplet dtype ----------------
__global__ void detect_kernel(const unsigned* __restrict__ w, int total_words) {
    __shared__ int zc, ts;
    if (threadIdx.x == 0) { zc = 0; ts = 0; }
    __syncthreads();
    int maxi = (total_words - 1) >> 1;
    int samples = maxi < 4096 ? maxi : 4096;
    int stride = samples > 0 ? (maxi / samples) : 1;
    if (stride < 1) stride = 1;
    int lz = 0, lt = 0;
    for (int s = threadIdx.x; s < samples; s += blockDim.x) {
        int i = s * stride;
        lt++;
        if (w[2 * i + 1] == 0u) lz++;
    }
    atomicAdd(&zc, lz);
    atomicAdd(&ts, lt);
    __syncthreads();
    if (threadIdx.x == 0) g_is64 = (2 * zc > ts) ? 1 : 0;
}

// ---------------- kernel 1: fp16 padded B images from W1 ----------------
__global__ void prep_B(const float* __restrict__ W1) {
    int idx = blockIdx.x * blockDim.x + threadIdx.x;
    if (idx >= 3 * 128 * 64) return;
    int j = idx / 8192;
    int rem = idx - j * 8192;
    int row = rem >> 6;
    int kp = rem & 63;
    int k = kp << 1;
    float v0 = W1[row * 384 + j * 128 + k];
    float v1 = W1[row * 384 + j * 128 + k + 1];
    *(__half2*)&g_Bf[j][(uint32_t)row * AST + k] = __floats2half2_rn(v0, v1);
}

// ---------------- kernel 2: P = h @ W1^T, fp16 mma, cp.async dbl-buffered B ----------------
#define SMEM_HALVES (128 * AST)
#define BBYTES (SMEM_HALVES * 2)            // 34816
#define SMEM_TOTAL (3 * BBYTES)             // 104448 bytes: A + B0 + B1

__global__ void __launch_bounds__(256, 2) gemm_P(const float* __restrict__ hmat) {
    extern __shared__ __half sm[];
    __half* A = sm;
    __half* Bbuf[2] = { sm + SMEM_HALVES, sm + 2 * SMEM_HALVES };

    int tid = threadIdx.x, w = tid >> 5, lane = tid & 31;
    int wm = w >> 2;
    int wn = w & 3;
    int base = blockIdx.x * 128;

    // prefetch B0 via cp.async (overlaps with the A load below)
    {
        const char* src = (const char*)g_Bf[0];
        char* dst = (char*)Bbuf[0];
        for (int i = tid; i < BBYTES / 16; i += 256) cpa16(dst + i * 16, src + i * 16);
        CP_COMMIT();
    }

    // Load + convert A tile [128 x 128] fp32 -> fp16 smem
    for (int p = tid; p < 128 * 64; p += 256) {
        int row = p >> 6, kp = p & 63;
        int node = base + row;
        float2 t = make_float2(0.f, 0.f);
        if (node < NNODES) t = *(const float2*)(hmat + (size_t)node * HF + (kp << 1));
        *(__half2*)&A[(uint32_t)row * AST + (kp << 1)] = __floats2half2_rn(t.x, t.y);
    }
    CP_WAIT0();
    __syncthreads();

    int a_row = wm * 64 + (lane & 15);
    int a_koff = (lane >> 4) << 3;
    int b_row = wn * 32 + (lane & 7) + ((lane >> 4) << 3);
    int b_koff = ((lane >> 3) & 1) << 3;

    for (int j = 0; j < 3; j++) {
        __half* B = Bbuf[j & 1];
        // prefetch next B into the other buffer (safe: all warps finished reading it
        // before the barrier that started this iteration)
        if (j < 2) {
            const char* src = (const char*)g_Bf[j + 1];
            char* dst = (char*)Bbuf[(j + 1) & 1];
            for (int i = tid; i < BBYTES / 16; i += 256) cpa16(dst + i * 16, src + i * 16);
            CP_COMMIT();
        }

        float acc[4][4][4];
        #pragma unroll
        for (int mt = 0; mt < 4; mt++)
            #pragma unroll
            for (int nt = 0; nt < 4; nt++)
                #pragma unroll
                for (int q = 0; q < 4; q++) acc[mt][nt][q] = 0.f;

        #pragma unroll
        for (int ks = 0; ks < 8; ks++) {
            int kb = ks * 16;
            uint32_t af[4][4], bf[2][4];
            #pragma unroll
            for (int mt = 0; mt < 4; mt++)
                ldsm4(af[mt], &A[(a_row + mt * 16) * AST + kb + a_koff]);
            #pragma unroll
            for (int bt = 0; bt < 2; bt++)
                ldsm4(bf[bt], &B[(b_row + bt * 16) * AST + kb + b_koff]);
            #pragma unroll
            for (int bt = 0; bt < 2; bt++)
                #pragma unroll
                for (int mt = 0; mt < 4; mt++) {
                    mma_f16(acc[mt][2 * bt], af[mt], bf[bt][0], bf[bt][1]);
                    mma_f16(acc[mt][2 * bt + 1], af[mt], bf[bt][2], bf[bt][3]);
                }
        }

        // epilogue: store fp16 P
        __half* Pj = g_P + (size_t)j * NODES_PAD * HF;
        int r0 = base + wm * 64 + (lane >> 2);
        int c0 = wn * 32 + (lane & 3) * 2;
        #pragma unroll
        for (int mt = 0; mt < 4; mt++) {
            int ra = r0 + mt * 16, rb = ra + 8;
            #pragma unroll
            for (int nt = 0; nt < 4; nt++) {
                int col = c0 + nt * 8;
                if (ra < NNODES)
                    *(__half2*)(Pj + (size_t)ra * HF + col) =
                        __floats2half2_rn(acc[mt][nt][0], acc[mt][nt][1]);
                if (rb < NNODES)
                    *(__half2*)(Pj + (size_t)rb * HF + col) =
                        __floats2half2_rn(acc[mt][nt][2], acc[mt][nt][3]);
            }
        }

        if (j < 2) CP_WAIT0();
        __syncthreads();
    }
}

// ---------------- kernel 3: gather + add + relu + layer-2 ----------------
// 16 lanes per triplet, TWO triplets in flight per group, persistent grid.
__global__ void __launch_bounds__(256, 4) mlp2_kernel(const void* __restrict__ trip,
                                                      const float* __restrict__ Wb1,
                                                      const float* __restrict__ W2,
                                                      const float* __restrict__ Wb2,
                                                      float* __restrict__ out, int T) {
    int tid = threadIdx.x;
    int sl = tid & 15;
    int grp = (int)((blockIdx.x * blockDim.x + tid) >> 4);
    int ngrp = (int)((gridDim.x * blockDim.x) >> 4);
    int is64 = g_is64;
    int sw = is64 ? 6 : 3, ew = is64 ? 2 : 1;
    int c8 = sl << 3;

    // weights hoisted as fp16 (12 regs)
    __half2 wb[4], w0h[4], w1h[4];
    {
        float4 a = *(const float4*)(Wb1 + c8), b = *(const float4*)(Wb1 + c8 + 4);
        wb[0] = __floats2half2_rn(a.x, a.y); wb[1] = __floats2half2_rn(a.z, a.w);
        wb[2] = __floats2half2_rn(b.x, b.y); wb[3] = __floats2half2_rn(b.z, b.w);
        a = *(const float4*)(W2 + c8); b = *(const float4*)(W2 + c8 + 4);
        w0h[0] = __floats2half2_rn(a.x, a.y); w0h[1] = __floats2half2_rn(a.z, a.w);
        w0h[2] = __floats2half2_rn(b.x, b.y); w0h[3] = __floats2half2_rn(b.z, b.w);
        a = *(const float4*)(W2 + HF + c8); b = *(const float4*)(W2 + HF + c8 + 4);
        w1h[0] = __floats2half2_rn(a.x, a.y); w1h[1] = __floats2half2_rn(a.z, a.w);
        w1h[2] = __floats2half2_rn(b.x, b.y); w1h[3] = __floats2half2_rn(b.z, b.w);
    }
    float c0 = Wb2[0], c1 = Wb2[1];

    const char* P0 = (const char*)g_P;
    const char* P1 = P0 + (size_t)NODES_PAD * HF * 2;
    const char* P2 = P1 + (size_t)NODES_PAD * HF * 2;
    const unsigned* tw = (const unsigned*)trip;
    uint32_t cb = (uint32_t)(c8 << 1);  // byte offset within row

    for (int t = grp * 2; t < T; t += ngrp * 2) {
        int bw = t * sw;
        unsigned i00 = tw[bw], i01 = tw[bw + ew], i02 = tw[bw + 2 * ew];
        bool two = (t + 1) < T;
        unsigned i10 = i00, i11 = i01, i12 = i02;
        if (two) { i10 = tw[bw + sw]; i11 = tw[bw + sw + ew]; i12 = tw[bw + sw + 2 * ew]; }

        // 6 gathers issued together (MLP=6)
        uint4 ua0 = *(const uint4*)(P0 + ((size_t)i00 << 8) + cb);
        uint4 ub0 = *(const uint4*)(P1 + ((size_t)i01 << 8) + cb);
        uint4 uc0 = *(const uint4*)(P2 + ((size_t)i02 << 8) + cb);
        uint4 ua1 = *(const uint4*)(P0 + ((size_t)i10 << 8) + cb);
        uint4 ub1 = *(const uint4*)(P1 + ((size_t)i11 << 8) + cb);
        uint4 uc1 = *(const uint4*)(P2 + ((size_t)i12 << 8) + cb);

        float acc00 = 0.f, acc01 = 0.f, acc10 = 0.f, acc11 = 0.f;
        #pragma unroll
        for (int q = 0; q < 4; q++) {
            float2 bias = __half22float2(wb[q]);
            float2 w0 = __half22float2(w0h[q]);
            float2 w1 = __half22float2(w1h[q]);
            // triplet 0
            {
                float2 fa = __half22float2(((const __half2*)&ua0)[q]);
                float2 fb = __half22float2(((const __half2*)&ub0)[q]);
                float2 fc = __half22float2(((const __half2*)&uc0)[q]);
                float hx = fmaxf(fa.x + fb.x + fc.x + bias.x, 0.f);
                float hy = fmaxf(fa.y + fb.y + fc.y + bias.y, 0.f);
                acc00 += hx * w0.x + hy * w0.y;
                acc01 += hx * w1.x + hy * w1.y;
            }
            // triplet 1
            {
                float2 fa = __half22float2(((const __half2*)&ua1)[q]);
                float2 fb = __half22float2(((const __half2*)&ub1)[q]);
                float2 fc = __half22float2(((const __half2*)&uc1)[q]);
                float hx = fmaxf(fa.x + fb.x + fc.x + bias.x, 0.f);
                float hy = fmaxf(fa.y + fb.y + fc.y + bias.y, 0.f);
                acc10 += hx * w0.x + hy * w0.y;
                acc11 += hx * w1.x + hy * w1.y;
            }
        }

        #pragma unroll
        for (int m = 8; m; m >>= 1) {
            acc00 += __shfl_xor_sync(0xffffffffu, acc00, m);
            acc01 += __shfl_xor_sync(0xffffffffu, acc01, m);
            acc10 += __shfl_xor_sync(0xffffffffu, acc10, m);
            acc11 += __shfl_xor_sync(0xffffffffu, acc11, m);
        }
        if (sl == 0) {
            if (two) {
                float4 o;
                o.x = acc00 + c0; o.y = acc01 + c1;
                o.z = acc10 + c0; o.w = acc11 + c1;
                *(float4*)(out + 2ll * t) = o;
            } else {
                float2 o;
                o.x = acc00 + c0; o.y = acc01 + c1;
                *(float2*)(out + 2ll * t) = o;
            }
        }
    }
}

// ---------------- launch ----------------
extern "C" void kernel_launch(void* const* d_in, const int* in_sizes, int n_in,
                              void* d_out, int out_size) {
    const float* hmat = (const float*)d_in[0];
    const void* trip = d_in[1];
    const float* W1w = (const float*)d_in[2];
    const float* W1b = (const float*)d_in[3];
    const float* W2w = (const float*)d_in[4];
    const float* W2b = (const float*)d_in[5];
    float* out = (float*)d_out;
    int T = in_sizes[1] / 3;

    static int smem_set = 0;
    if (!smem_set) {
        cudaFuncSetAttribute(gemm_P, cudaFuncAttributeMaxDynamicSharedMemorySize, SMEM_TOTAL);
        smem_set = 1;
    }

    detect_kernel<<<1, 256>>>((const unsigned*)trip, in_sizes[1]);
    prep_B<<<(3 * 128 * 64 + 255) / 256, 256>>>(W1w);
    gemm_P<<<MTILES, 256, SMEM_TOTAL>>>(hmat);
    mlp2_kernel<<<592, 256>>>(trip, W1b, W2w, W2b, out, T);
}